// round 1
// baseline (speedup 1.0000x reference)
#include <cuda_runtime.h>
#include <math.h>

#define B_   32
#define T_   64
#define TD_  48
#define H_   512
#define V_   16000
#define BT_  (B_*T_)      // 2048
#define MY_  (TD_*B_)     // 1536

// ---------------- scratch (no cudaMalloc allowed) ----------------
__device__ float g_w1   [BT_*H_];   // enc @ W1^T   [2048,512]
__device__ float g_th   [BT_*H_];   // tanh buffer (also holds enc@W2^T during precompute)
__device__ float g_u    [BT_*H_];   // attention logits [2048,512]
__device__ float g_attns[B_*H_];    // [32,512]
__device__ float g_stateT[H_*B_];   // state transposed [512,32]
__device__ float g_xT    [H_*B_];   // x transposed [512,32]
__device__ float g_giT [3*H_*B_];   // gi transposed [1536,32]
__device__ float g_ghT [3*H_*B_];   // gh transposed [1536,32]
__device__ float g_q    [B_*H_];    // state @ W2^T [32,512]
__device__ float g_y    [MY_*H_];   // (state+attns) rows per step [1536,512]

// ---------------- tiled fp32 NT GEMM: C[M,N] = A[M,K] * B[N,K]^T (+bias) ------
// BM=64, BN=64, BK=16, 128 threads, 8x4 microtile. M%64==0, N%64==0, K%16==0.
template<bool BIAS>
__global__ void __launch_bounds__(128) gemm_nt(
    const float* __restrict__ A, const float* __restrict__ Bm,
    const float* __restrict__ bias, float* __restrict__ C,
    int M, int N, int K)
{
    constexpr int BM = 64, BN = 64, BK = 16;
    __shared__ __align__(16) float As[BK][BM + 4];
    __shared__ __align__(16) float Bs[BK][BN + 4];
    const int tid = threadIdx.x;
    const int bm = blockIdx.y * BM, bn = blockIdx.x * BN;
    const int tx = tid & 15, ty = tid >> 4;     // tx: n (x4), ty: m (x8)

    float acc[8][4];
#pragma unroll
    for (int i = 0; i < 8; i++)
#pragma unroll
        for (int j = 0; j < 4; j++) acc[i][j] = 0.f;

    for (int k0 = 0; k0 < K; k0 += BK) {
#pragma unroll
        for (int i = 0; i < 8; i++) {
            int e = tid + i * 128;
            int r = e >> 4, c = e & 15;
            As[c][r] = A[(size_t)(bm + r) * K + k0 + c];
            Bs[c][r] = Bm[(size_t)(bn + r) * K + k0 + c];
        }
        __syncthreads();
#pragma unroll
        for (int k = 0; k < BK; k++) {
            float4 a0 = *reinterpret_cast<const float4*>(&As[k][ty * 8]);
            float4 a1 = *reinterpret_cast<const float4*>(&As[k][ty * 8 + 4]);
            float4 b0 = *reinterpret_cast<const float4*>(&Bs[k][tx * 4]);
            float am[8] = {a0.x, a0.y, a0.z, a0.w, a1.x, a1.y, a1.z, a1.w};
            float bv[4] = {b0.x, b0.y, b0.z, b0.w};
#pragma unroll
            for (int i = 0; i < 8; i++)
#pragma unroll
                for (int j = 0; j < 4; j++) acc[i][j] += am[i] * bv[j];
        }
        __syncthreads();
    }
#pragma unroll
    for (int i = 0; i < 8; i++) {
        int m = bm + ty * 8 + i;
#pragma unroll
        for (int j = 0; j < 4; j++) {
            int n = bn + tx * 4 + j;
            float v = acc[i][j];
            if (BIAS) v += bias[n];
            C[(size_t)m * N + n] = v;
        }
    }
}

// th[m,k] = tanh(w1[m,k] + q[b(m),k]),  b(m) = m/64  (per-step broadcast query)
__global__ void tanh_bcast(const float* __restrict__ w1, const float* __restrict__ q,
                           float* __restrict__ th)
{
    int g = blockIdx.x * blockDim.x + threadIdx.x;
    if (g >= BT_ * H_) return;
    int m = g >> 9, k = g & 511;
    th[g] = tanhf(w1[g] + q[((m >> 6) << 9) + k]);
}

// in-place: th[m,k] = tanh(w1[m,k] + th[m,k])  (full q2 for attns0)
__global__ void tanh_full(const float* __restrict__ w1, float* __restrict__ th)
{
    int g = blockIdx.x * blockDim.x + threadIdx.x;
    if (g >= BT_ * H_) return;
    th[g] = tanhf(w1[g] + th[g]);
}

// skinny GEMM pair, warp per output row, lane = batch:
//   O1[n][b] = sum_k W1[n][k]*A1[k][b] + b1[n]   (n < 1536)
//   O2[n][b] = sum_k W2[n][k]*A2[k][b] + b2[n]
__global__ void skinny2(const float* __restrict__ Wa, const float* __restrict__ Aa,
                        const float* __restrict__ ba, float* __restrict__ Oa,
                        const float* __restrict__ Wb, const float* __restrict__ Ab,
                        const float* __restrict__ bb, float* __restrict__ Ob)
{
    int warp = (blockIdx.x * blockDim.x + threadIdx.x) >> 5;
    int lane = threadIdx.x & 31;
    const float *W, *AT, *bias; float* O; int n;
    if (warp < 3 * H_) { W = Wa; AT = Aa; bias = ba; O = Oa; n = warp; }
    else               { W = Wb; AT = Ab; bias = bb; O = Ob; n = warp - 3 * H_; }
    if (n >= 3 * H_) return;
    const float* wrow = W + (size_t)n * H_;
    float acc = 0.f;
#pragma unroll 4
    for (int k = 0; k < H_; k += 4) {
        float4 w = *reinterpret_cast<const float4*>(wrow + k);
        acc += w.x * AT[(k + 0) * 32 + lane];
        acc += w.y * AT[(k + 1) * 32 + lane];
        acc += w.z * AT[(k + 2) * 32 + lane];
        acc += w.w * AT[(k + 3) * 32 + lane];
    }
    O[n * 32 + lane] = acc + bias[n];
}

// q[b][i] = sum_k W2[i][k] * stateT[k][b]   (warp per i, lane = b)
__global__ void qkern(const float* __restrict__ W2, const float* __restrict__ stateT,
                      float* __restrict__ q)
{
    int warp = (blockIdx.x * blockDim.x + threadIdx.x) >> 5;
    int lane = threadIdx.x & 31;
    if (warp >= H_) return;
    const float* wrow = W2 + (size_t)warp * H_;
    float acc = 0.f;
#pragma unroll 4
    for (int k = 0; k < H_; k += 4) {
        float4 w = *reinterpret_cast<const float4*>(wrow + k);
        acc += w.x * stateT[(k + 0) * 32 + lane];
        acc += w.y * stateT[(k + 1) * 32 + lane];
        acc += w.z * stateT[(k + 2) * 32 + lane];
        acc += w.w * stateT[(k + 3) * 32 + lane];
    }
    q[lane * H_ + warp] = acc;
}

// xT[h][b] = sum_k Wr[b][k]*dec[k][t] + sum_k Wr[b][32+k]*attns[k][h] + br[b]
__global__ void xkern(const float* __restrict__ Wr, const float* __restrict__ br,
                      const float* __restrict__ dec, int t,
                      const float* __restrict__ attns, float* __restrict__ xT)
{
    int warp = (blockIdx.x * blockDim.x + threadIdx.x) >> 5;
    int lane = threadIdx.x & 31;   // lane = b
    if (warp >= H_) return;
    int h = warp;
    float c = 0.f;
#pragma unroll
    for (int k = 0; k < 32; k++) c += Wr[lane * 64 + k] * dec[k * TD_ + t];
    float acc = 0.f;
#pragma unroll
    for (int k = 0; k < 32; k++) acc += Wr[lane * 64 + 32 + k] * attns[k * H_ + h];
    xT[h * 32 + lane] = c + acc + br[lane];
}

// GRU gates (torch GRUCell semantics), everything transposed [·,32]
__global__ void gatek(const float* __restrict__ giT, const float* __restrict__ ghT,
                      float* __restrict__ stateT)
{
    int g = blockIdx.x * blockDim.x + threadIdx.x;
    if (g >= H_ * 32) return;
    int b = g & 31, h = g >> 5;
    float ir = giT[h * 32 + b],          hr = ghT[h * 32 + b];
    float iz = giT[(H_ + h) * 32 + b],   hz = ghT[(H_ + h) * 32 + b];
    float in = giT[(2*H_ + h) * 32 + b], hn = ghT[(2*H_ + h) * 32 + b];
    float r = 1.f / (1.f + expf(-(ir + hr)));
    float z = 1.f / (1.f + expf(-(iz + hz)));
    float n = tanhf(in + r * hn);
    float hold = stateT[g];
    stateT[g] = (1.f - z) * n + z * hold;
}

// per-b block: softmax of u[b,t,:] over hidden dim, weighted-sum over t with enc.
// Also fuses y[step*32+b][i] = stateT[i][b] + attns[b][i].
__global__ void __launch_bounds__(512) attnsk(
    const float* __restrict__ u, const float* __restrict__ enc,
    const float* __restrict__ stateT, float* __restrict__ attns,
    float* __restrict__ y, int step, int writeY)
{
    int b = blockIdx.x;
    __shared__ float smax[T_], sinv[T_];
    int tid = threadIdx.x, lane = tid & 31, warp = tid >> 5;   // 16 warps
#pragma unroll
    for (int r = 0; r < 4; r++) {
        int t = warp * 4 + r;
        const float* row = u + (size_t)(b * T_ + t) * H_;
        float vals[16], mx = -1e30f;
#pragma unroll
        for (int j = 0; j < 16; j++) { vals[j] = row[j * 32 + lane]; mx = fmaxf(mx, vals[j]); }
#pragma unroll
        for (int off = 16; off; off >>= 1) mx = fmaxf(mx, __shfl_xor_sync(0xffffffffu, mx, off));
        float s = 0.f;
#pragma unroll
        for (int j = 0; j < 16; j++) s += expf(vals[j] - mx);
#pragma unroll
        for (int off = 16; off; off >>= 1) s += __shfl_xor_sync(0xffffffffu, s, off);
        if (lane == 0) { smax[t] = mx; sinv[t] = 1.f / s; }
    }
    __syncthreads();
    int i = tid;            // 0..511
    float acc = 0.f;
#pragma unroll 4
    for (int t = 0; t < T_; t++) {
        size_t idx = (size_t)(b * T_ + t) * H_ + i;
        acc += expf(u[idx] - smax[t]) * sinv[t] * enc[idx];
    }
    attns[b * H_ + i] = acc;
    if (writeY) y[(size_t)(step * B_ + b) * H_ + i] = stateT[i * 32 + b] + acc;
}

__global__ void zerok(float* __restrict__ p, int n)
{
    int g = blockIdx.x * blockDim.x + threadIdx.x;
    if (g < n) p[g] = 0.f;
}

__global__ void stateout(const float* __restrict__ stateT, float* __restrict__ out)
{
    int g = blockIdx.x * blockDim.x + threadIdx.x;
    if (g >= B_ * H_) return;
    int h = g & 511, b = g >> 9;
    out[b * H_ + h] = stateT[h * 32 + b];
}

extern "C" void kernel_launch(void* const* d_in, const int* in_sizes, int n_in,
                              void* d_out, int out_size)
{
    const float* enc  = (const float*)d_in[0];
    const float* dec  = (const float*)d_in[1];
    const float* W1   = (const float*)d_in[2];
    const float* W2   = (const float*)d_in[3];
    const float* vT   = (const float*)d_in[4];
    const float* Wr   = (const float*)d_in[5];
    const float* br   = (const float*)d_in[6];
    const float* Wih1 = (const float*)d_in[7];
    const float* Whh1 = (const float*)d_in[8];
    const float* bih1 = (const float*)d_in[9];
    const float* bhh1 = (const float*)d_in[10];
    const float* Wih2 = (const float*)d_in[11];
    const float* Whh2 = (const float*)d_in[12];
    const float* bih2 = (const float*)d_in[13];
    const float* bhh2 = (const float*)d_in[14];
    const float* Wout = (const float*)d_in[15];
    const float* bout = (const float*)d_in[16];
    float* out = (float*)d_out;

    float *w1, *th, *u, *attns, *stateT, *xT, *giT, *ghT, *q, *y;
    cudaGetSymbolAddress((void**)&w1,     g_w1);
    cudaGetSymbolAddress((void**)&th,     g_th);
    cudaGetSymbolAddress((void**)&u,      g_u);
    cudaGetSymbolAddress((void**)&attns,  g_attns);
    cudaGetSymbolAddress((void**)&stateT, g_stateT);
    cudaGetSymbolAddress((void**)&xT,     g_xT);
    cudaGetSymbolAddress((void**)&giT,    g_giT);
    cudaGetSymbolAddress((void**)&ghT,    g_ghT);
    cudaGetSymbolAddress((void**)&q,      g_q);
    cudaGetSymbolAddress((void**)&y,      g_y);

    const dim3 gemmSmall(H_ / 64, BT_ / 64);   // (8, 32)
    const int EW = BT_ * H_;                   // 1M elements

    // ---- precompute: w1 = enc@W1^T ; th = enc@W2^T ; th = tanh(w1+th) ; u = th@vT^T ----
    gemm_nt<false><<<gemmSmall, 128>>>(enc, W1, nullptr, w1, BT_, H_, H_);
    gemm_nt<false><<<gemmSmall, 128>>>(enc, W2, nullptr, th, BT_, H_, H_);
    tanh_full<<<(EW + 255) / 256, 256>>>(w1, th);
    gemm_nt<false><<<gemmSmall, 128>>>(th, vT, nullptr, u, BT_, H_, H_);
    zerok<<<64, 256>>>(stateT, H_ * 32);
    attnsk<<<B_, 512>>>(u, enc, stateT, attns, y, 0, 0);

    // ---- sequential decode ----
    for (int t = 0; t < TD_; t++) {
        xkern<<<128, 128>>>(Wr, br, dec, t, attns, xT);
        skinny2<<<384, 256>>>(Wih1, xT, bih1, giT, Whh1, stateT, bhh1, ghT);
        gatek<<<64, 256>>>(giT, ghT, stateT);
        skinny2<<<384, 256>>>(Wih2, xT, bih2, giT, Whh2, stateT, bhh2, ghT);
        gatek<<<64, 256>>>(giT, ghT, stateT);
        qkern<<<128, 128>>>(W2, stateT, q);
        tanh_bcast<<<(EW + 255) / 256, 256>>>(w1, q, th);
        gemm_nt<false><<<gemmSmall, 128>>>(th, vT, nullptr, u, BT_, H_, H_);
        attnsk<<<B_, 512>>>(u, enc, stateT, attns, y, t, 1);
    }

    // ---- batched output projection: out[t,b,:] = y[t*32+b,:] @ Wout^T + bout ----
    gemm_nt<true><<<dim3(V_ / 64, MY_ / 64), 128>>>(y, Wout, bout, out, MY_, V_, H_);

    // ---- final state (second element of the output tuple) ----
    if (out_size >= TD_ * B_ * V_ + B_ * H_) {
        stateout<<<64, 256>>>(stateT, out + (size_t)TD_ * B_ * V_);
    }
}

// round 3
// speedup vs baseline: 1.0121x; 1.0121x over previous
#include <cuda_runtime.h>
#include <math.h>

#define B_   32
#define T_   64
#define TD_  48
#define H_   512
#define V_   16000
#define BT_  (B_*T_)      // 2048
#define MY_  (TD_*B_)     // 1536

// ---------------- scratch (no cudaMalloc allowed) ----------------
__device__ float g_w1   [BT_*H_];   // enc @ W1^T   [2048,512]
__device__ float g_th   [BT_*H_];   // tanh buffer (also holds enc@W2^T during precompute)
__device__ float g_u    [BT_*H_];   // attention logits [2048,512]
__device__ float g_attns[B_*H_];    // [32,512]
__device__ float g_stateT[H_*B_];   // state transposed [512,32]
__device__ float g_xT    [H_*B_];   // x transposed [512,32]
__device__ float g_giT [3*H_*B_];   // gi transposed [1536,32]
__device__ float g_ghT [3*H_*B_];   // gh transposed [1536,32]
__device__ float g_q    [B_*H_];    // state @ W2^T [32,512]
__device__ float g_y    [MY_*H_];   // (state+attns) rows per step [1536,512]

// ---------------- tiled fp32 NT GEMM: C[M,N] = A[M,K] * B[N,K]^T (+bias) ------
// BM=64, BN=64, BK=16, 128 threads, 8x4 microtile. M%64==0, N%64==0, K%16==0.
template<bool BIAS>
__global__ void __launch_bounds__(128) gemm_nt(
    const float* __restrict__ A, const float* __restrict__ Bm,
    const float* __restrict__ bias, float* __restrict__ C,
    int M, int N, int K)
{
    constexpr int BM = 64, BN = 64, BK = 16;
    __shared__ __align__(16) float As[BK][BM + 4];
    __shared__ __align__(16) float Bs[BK][BN + 4];
    const int tid = threadIdx.x;
    const int bm = blockIdx.y * BM, bn = blockIdx.x * BN;
    const int tx = tid & 15, ty = tid >> 4;     // tx: n (x4), ty: m (x8)

    float acc[8][4];
#pragma unroll
    for (int i = 0; i < 8; i++)
#pragma unroll
        for (int j = 0; j < 4; j++) acc[i][j] = 0.f;

    for (int k0 = 0; k0 < K; k0 += BK) {
#pragma unroll
        for (int i = 0; i < 8; i++) {
            int e = tid + i * 128;
            int r = e >> 4, c = e & 15;
            As[c][r] = A[(size_t)(bm + r) * K + k0 + c];
            Bs[c][r] = Bm[(size_t)(bn + r) * K + k0 + c];
        }
        __syncthreads();
#pragma unroll
        for (int k = 0; k < BK; k++) {
            float4 a0 = *reinterpret_cast<const float4*>(&As[k][ty * 8]);
            float4 a1 = *reinterpret_cast<const float4*>(&As[k][ty * 8 + 4]);
            float4 b0 = *reinterpret_cast<const float4*>(&Bs[k][tx * 4]);
            float am[8] = {a0.x, a0.y, a0.z, a0.w, a1.x, a1.y, a1.z, a1.w};
            float bv[4] = {b0.x, b0.y, b0.z, b0.w};
#pragma unroll
            for (int i = 0; i < 8; i++)
#pragma unroll
                for (int j = 0; j < 4; j++) acc[i][j] += am[i] * bv[j];
        }
        __syncthreads();
    }
#pragma unroll
    for (int i = 0; i < 8; i++) {
        int m = bm + ty * 8 + i;
#pragma unroll
        for (int j = 0; j < 4; j++) {
            int n = bn + tx * 4 + j;
            float v = acc[i][j];
            if (BIAS) v += bias[n];
            C[(size_t)m * N + n] = v;
        }
    }
}

// th[m,k] = tanh(w1[m,k] + q[b(m),k]),  b(m) = m/64  (per-step broadcast query)
__global__ void tanh_bcast(const float* __restrict__ w1, const float* __restrict__ q,
                           float* __restrict__ th)
{
    int g = blockIdx.x * blockDim.x + threadIdx.x;
    if (g >= BT_ * H_) return;
    int m = g >> 9, k = g & 511;
    th[g] = tanhf(w1[g] + q[((m >> 6) << 9) + k]);
}

// in-place: th[m,k] = tanh(w1[m,k] + th[m,k])  (full q2 for attns0)
__global__ void tanh_full(const float* __restrict__ w1, float* __restrict__ th)
{
    int g = blockIdx.x * blockDim.x + threadIdx.x;
    if (g >= BT_ * H_) return;
    th[g] = tanhf(w1[g] + th[g]);
}

// skinny GEMM pair, warp per output row, lane = batch:
//   O1[n][b] = sum_k W1[n][k]*A1[k][b] + b1[n]   (n < 1536)
//   O2[n][b] = sum_k W2[n][k]*A2[k][b] + b2[n]
__global__ void skinny2(const float* __restrict__ Wa, const float* __restrict__ Aa,
                        const float* __restrict__ ba, float* __restrict__ Oa,
                        const float* __restrict__ Wb, const float* __restrict__ Ab,
                        const float* __restrict__ bb, float* __restrict__ Ob)
{
    int warp = (blockIdx.x * blockDim.x + threadIdx.x) >> 5;
    int lane = threadIdx.x & 31;
    const float *W, *AT, *bias; float* O; int n;
    if (warp < 3 * H_) { W = Wa; AT = Aa; bias = ba; O = Oa; n = warp; }
    else               { W = Wb; AT = Ab; bias = bb; O = Ob; n = warp - 3 * H_; }
    if (n >= 3 * H_) return;
    const float* wrow = W + (size_t)n * H_;
    float acc = 0.f;
#pragma unroll 4
    for (int k = 0; k < H_; k += 4) {
        float4 w = *reinterpret_cast<const float4*>(wrow + k);
        acc += w.x * AT[(k + 0) * 32 + lane];
        acc += w.y * AT[(k + 1) * 32 + lane];
        acc += w.z * AT[(k + 2) * 32 + lane];
        acc += w.w * AT[(k + 3) * 32 + lane];
    }
    O[n * 32 + lane] = acc + bias[n];
}

// q[b][i] = sum_k W2[i][k] * stateT[k][b]   (warp per i, lane = b)
__global__ void qkern(const float* __restrict__ W2, const float* __restrict__ stateT,
                      float* __restrict__ q)
{
    int warp = (blockIdx.x * blockDim.x + threadIdx.x) >> 5;
    int lane = threadIdx.x & 31;
    if (warp >= H_) return;
    const float* wrow = W2 + (size_t)warp * H_;
    float acc = 0.f;
#pragma unroll 4
    for (int k = 0; k < H_; k += 4) {
        float4 w = *reinterpret_cast<const float4*>(wrow + k);
        acc += w.x * stateT[(k + 0) * 32 + lane];
        acc += w.y * stateT[(k + 1) * 32 + lane];
        acc += w.z * stateT[(k + 2) * 32 + lane];
        acc += w.w * stateT[(k + 3) * 32 + lane];
    }
    q[lane * H_ + warp] = acc;
}

// xT[h][b] = sum_k Wr[b][k]*dec[k][t] + sum_k Wr[b][32+k]*attns[k][h] + br[b]
__global__ void xkern(const float* __restrict__ Wr, const float* __restrict__ br,
                      const float* __restrict__ dec, int t,
                      const float* __restrict__ attns, float* __restrict__ xT)
{
    int warp = (blockIdx.x * blockDim.x + threadIdx.x) >> 5;
    int lane = threadIdx.x & 31;   // lane = b
    if (warp >= H_) return;
    int h = warp;
    float c = 0.f;
#pragma unroll
    for (int k = 0; k < 32; k++) c += Wr[lane * 64 + k] * dec[k * TD_ + t];
    float acc = 0.f;
#pragma unroll
    for (int k = 0; k < 32; k++) acc += Wr[lane * 64 + 32 + k] * attns[k * H_ + h];
    xT[h * 32 + lane] = c + acc + br[lane];
}

// GRU gates (torch GRUCell semantics), everything transposed [·,32]
__global__ void gatek(const float* __restrict__ giT, const float* __restrict__ ghT,
                      float* __restrict__ stateT)
{
    int g = blockIdx.x * blockDim.x + threadIdx.x;
    if (g >= H_ * 32) return;
    int b = g & 31, h = g >> 5;
    float ir = giT[h * 32 + b],          hr = ghT[h * 32 + b];
    float iz = giT[(H_ + h) * 32 + b],   hz = ghT[(H_ + h) * 32 + b];
    float in = giT[(2*H_ + h) * 32 + b], hn = ghT[(2*H_ + h) * 32 + b];
    float r = 1.f / (1.f + expf(-(ir + hr)));
    float z = 1.f / (1.f + expf(-(iz + hz)));
    float n = tanhf(in + r * hn);
    float hold = stateT[g];
    stateT[g] = (1.f - z) * n + z * hold;
}

// per-b block: softmax of u[b,t,:] over hidden dim, weighted-sum over t with enc.
// Also fuses y[step*32+b][i] = stateT[i][b] + attns[b][i].
__global__ void __launch_bounds__(512) attnsk(
    const float* __restrict__ u, const float* __restrict__ enc,
    const float* __restrict__ stateT, float* __restrict__ attns,
    float* __restrict__ y, int step, int writeY)
{
    int b = blockIdx.x;
    __shared__ float smax[T_], sinv[T_];
    int tid = threadIdx.x, lane = tid & 31, warp = tid >> 5;   // 16 warps
#pragma unroll
    for (int r = 0; r < 4; r++) {
        int t = warp * 4 + r;
        const float* row = u + (size_t)(b * T_ + t) * H_;
        float vals[16], mx = -1e30f;
#pragma unroll
        for (int j = 0; j < 16; j++) { vals[j] = row[j * 32 + lane]; mx = fmaxf(mx, vals[j]); }
#pragma unroll
        for (int off = 16; off; off >>= 1) mx = fmaxf(mx, __shfl_xor_sync(0xffffffffu, mx, off));
        float s = 0.f;
#pragma unroll
        for (int j = 0; j < 16; j++) s += expf(vals[j] - mx);
#pragma unroll
        for (int off = 16; off; off >>= 1) s += __shfl_xor_sync(0xffffffffu, s, off);
        if (lane == 0) { smax[t] = mx; sinv[t] = 1.f / s; }
    }
    __syncthreads();
    int i = tid;            // 0..511
    float acc = 0.f;
#pragma unroll 4
    for (int t = 0; t < T_; t++) {
        size_t idx = (size_t)(b * T_ + t) * H_ + i;
        acc += expf(u[idx] - smax[t]) * sinv[t] * enc[idx];
    }
    attns[b * H_ + i] = acc;
    if (writeY) y[(size_t)(step * B_ + b) * H_ + i] = stateT[i * 32 + b] + acc;
}

__global__ void zerok(float* __restrict__ p, int n)
{
    int g = blockIdx.x * blockDim.x + threadIdx.x;
    if (g < n) p[g] = 0.f;
}

__global__ void stateout(const float* __restrict__ stateT, float* __restrict__ out)
{
    int g = blockIdx.x * blockDim.x + threadIdx.x;
    if (g >= B_ * H_) return;
    int h = g & 511, b = g >> 9;
    out[b * H_ + h] = stateT[h * 32 + b];
}

extern "C" void kernel_launch(void* const* d_in, const int* in_sizes, int n_in,
                              void* d_out, int out_size)
{
    const float* enc  = (const float*)d_in[0];
    const float* dec  = (const float*)d_in[1];
    const float* W1   = (const float*)d_in[2];
    const float* W2   = (const float*)d_in[3];
    const float* vT   = (const float*)d_in[4];
    const float* Wr   = (const float*)d_in[5];
    const float* br   = (const float*)d_in[6];
    const float* Wih1 = (const float*)d_in[7];
    const float* Whh1 = (const float*)d_in[8];
    const float* bih1 = (const float*)d_in[9];
    const float* bhh1 = (const float*)d_in[10];
    const float* Wih2 = (const float*)d_in[11];
    const float* Whh2 = (const float*)d_in[12];
    const float* bih2 = (const float*)d_in[13];
    const float* bhh2 = (const float*)d_in[14];
    const float* Wout = (const float*)d_in[15];
    const float* bout = (const float*)d_in[16];
    float* out = (float*)d_out;

    float *w1, *th, *u, *attns, *stateT, *xT, *giT, *ghT, *q, *y;
    cudaGetSymbolAddress((void**)&w1,     g_w1);
    cudaGetSymbolAddress((void**)&th,     g_th);
    cudaGetSymbolAddress((void**)&u,      g_u);
    cudaGetSymbolAddress((void**)&attns,  g_attns);
    cudaGetSymbolAddress((void**)&stateT, g_stateT);
    cudaGetSymbolAddress((void**)&xT,     g_xT);
    cudaGetSymbolAddress((void**)&giT,    g_giT);
    cudaGetSymbolAddress((void**)&ghT,    g_ghT);
    cudaGetSymbolAddress((void**)&q,      g_q);
    cudaGetSymbolAddress((void**)&y,      g_y);

    const dim3 gemmSmall(H_ / 64, BT_ / 64);   // (8, 32)
    const int EW = BT_ * H_;                   // 1M elements

    // ---- precompute: w1 = enc@W1^T ; th = enc@W2^T ; th = tanh(w1+th) ; u = th@vT^T ----
    gemm_nt<false><<<gemmSmall, 128>>>(enc, W1, nullptr, w1, BT_, H_, H_);
    gemm_nt<false><<<gemmSmall, 128>>>(enc, W2, nullptr, th, BT_, H_, H_);
    tanh_full<<<(EW + 255) / 256, 256>>>(w1, th);
    gemm_nt<false><<<gemmSmall, 128>>>(th, vT, nullptr, u, BT_, H_, H_);
    zerok<<<64, 256>>>(stateT, H_ * 32);
    attnsk<<<B_, 512>>>(u, enc, stateT, attns, y, 0, 0);

    // ---- sequential decode ----
    for (int t = 0; t < TD_; t++) {
        xkern<<<128, 128>>>(Wr, br, dec, t, attns, xT);
        skinny2<<<384, 256>>>(Wih1, xT, bih1, giT, Whh1, stateT, bhh1, ghT);
        gatek<<<64, 256>>>(giT, ghT, stateT);
        skinny2<<<384, 256>>>(Wih2, xT, bih2, giT, Whh2, stateT, bhh2, ghT);
        gatek<<<64, 256>>>(giT, ghT, stateT);
        qkern<<<128, 128>>>(W2, stateT, q);
        tanh_bcast<<<(EW + 255) / 256, 256>>>(w1, q, th);
        gemm_nt<false><<<gemmSmall, 128>>>(th, vT, nullptr, u, BT_, H_, H_);
        attnsk<<<B_, 512>>>(u, enc, stateT, attns, y, t, 1);
    }

    // ---- batched output projection: out[t,b,:] = y[t*32+b,:] @ Wout^T + bout ----
    gemm_nt<true><<<dim3(V_ / 64, MY_ / 64), 128>>>(y, Wout, bout, out, MY_, V_, H_);

    // ---- final state (second element of the output tuple) ----
    if (out_size >= TD_ * B_ * V_ + B_ * H_) {
        stateout<<<64, 256>>>(stateT, out + (size_t)TD_ * B_ * V_);
    }
}